// round 7
// baseline (speedup 1.0000x reference)
#include <cuda_runtime.h>
#include <cstdint>

// out[b, p, d] = x[b, p] * W[p, d] + bias[p, d]
// B=64, P=2000, D=512 (fp32). HBM-write-bound: 262MB out, ~6.74TB/s achieved
// (~97% of pure-write wall). Converged structure: thread owns a d-chunk of one
// p-row x 8 batch rows; W/b loaded once (L2-resident), .cs streaming stores.
// This round: 256-bit ld/st (sm_100+ v8.f32) — thread owns a (p, d8) chunk,
// halving STG count / L1 wavefronts (L1 was 71% busy).

#define B_DIM 64
#define P_DIM 2000
#define D_DIM 512
#define D8 (D_DIM / 8)              // 64 float8-chunks per row
#define PD8 (P_DIM * D8)            // 128000
#define B_CHUNK 8                   // batches per thread
#define N_CHUNKS (B_DIM / B_CHUNK)  // 8
#define TPB 128

__device__ __forceinline__ void ldg256(const float* p, float o[8]) {
    asm volatile("ld.global.nc.v8.f32 {%0,%1,%2,%3,%4,%5,%6,%7}, [%8];"
                 : "=f"(o[0]), "=f"(o[1]), "=f"(o[2]), "=f"(o[3]),
                   "=f"(o[4]), "=f"(o[5]), "=f"(o[6]), "=f"(o[7])
                 : "l"(p));
}

__device__ __forceinline__ void stg256_cs(float* p, const float o[8]) {
    asm volatile("st.global.cs.v8.f32 [%0], {%1,%2,%3,%4,%5,%6,%7,%8};"
                 :: "l"(p),
                    "f"(o[0]), "f"(o[1]), "f"(o[2]), "f"(o[3]),
                    "f"(o[4]), "f"(o[5]), "f"(o[6]), "f"(o[7])
                 : "memory");
}

__global__ __launch_bounds__(TPB) void feature_expander_kernel(
    const float* __restrict__ x,      // [B, P]
    const float* __restrict__ W,      // [P, D]
    const float* __restrict__ bias,   // [P, D]
    float* __restrict__ out)          // [B, P, D]
{
    int idx = blockIdx.x * TPB + threadIdx.x;   // < PD8 always (1000*128)
    int p = idx >> 6;                           // idx / 64
    int b0 = blockIdx.y * B_CHUNK;

    float w[8], bv[8];
    ldg256(W + (size_t)idx * 8, w);
    ldg256(bias + (size_t)idx * 8, bv);

    const float* xp = x + b0 * P_DIM + p;
    float* op = out + (size_t)b0 * P_DIM * D_DIM + (size_t)idx * 8;

    #pragma unroll
    for (int i = 0; i < B_CHUNK; i++) {
        float xv = __ldg(xp + i * P_DIM);
        float o[8];
        #pragma unroll
        for (int j = 0; j < 8; j++)
            o[j] = fmaf(xv, w[j], bv[j]);
        stg256_cs(op + (size_t)i * P_DIM * D_DIM, o);
    }
}

extern "C" void kernel_launch(void* const* d_in, const int* in_sizes, int n_in,
                              void* d_out, int out_size) {
    const float* x  = (const float*)d_in[0];
    const float* W  = (const float*)d_in[1];
    const float* bb = (const float*)d_in[2];
    float* out = (float*)d_out;

    dim3 grid(PD8 / TPB, N_CHUNKS);   // 1000 x 8
    feature_expander_kernel<<<grid, TPB>>>(x, W, bb, out);
}

// round 8
// speedup vs baseline: 1.1112x; 1.1112x over previous
#include <cuda_runtime.h>

// out[b, p, d] = x[b, p] * W[p, d] + bias[p, d]
// B=64, P=2000, D=512 (fp32).
//
// CONVERGED at the HBM write roofline: 262MB output / ~39.4us = ~6.65TB/s of
// pure writes (~96% of the achievable write wall on HBM3e; reads are ~8.5MB,
// L2-resident). Full sweep: B_CHUNK {4:60.1, 8:40.0, 16:41.0}us,
// TPB {128:40.4, 256:40.0}us, persistent grid 45.4us (HW scheduler wins),
// 256-bit stores 45.1us (halved thread count -> lost store MLP).
//
// Shape: thread = one (p, d4) float4 column x 8 batch rows. W/b loaded once
// per thread (re-reads are L2 hits; W+b = 8MB resident). x is a per-warp
// broadcast load (L1 hit). .cs streaming stores keep the 262MB output stream
// from evicting the resident inputs.

#define B_DIM 64
#define P_DIM 2000
#define D_DIM 512
#define D4 (D_DIM / 4)              // 128
#define PD4 (P_DIM * D4)            // 256000
#define B_CHUNK 8                   // batches per thread
#define N_CHUNKS (B_DIM / B_CHUNK)  // 8

__global__ __launch_bounds__(256) void feature_expander_kernel(
    const float* __restrict__ x,      // [B, P]
    const float4* __restrict__ W,     // [P, D/4]
    const float4* __restrict__ bias,  // [P, D/4]
    float4* __restrict__ out)         // [B, P, D/4]
{
    int idx = blockIdx.x * blockDim.x + threadIdx.x;   // < PD4 always (1000*256)
    int p = idx >> 7;                                  // idx / 128
    int b0 = blockIdx.y * B_CHUNK;

    float4 w = __ldg(&W[idx]);
    float4 bv = __ldg(&bias[idx]);

    const float* xp = x + b0 * P_DIM + p;
    float4* op = out + (size_t)b0 * PD4 + idx;

    #pragma unroll
    for (int i = 0; i < B_CHUNK; i++) {
        float xv = __ldg(xp + i * P_DIM);
        float4 o;
        o.x = fmaf(xv, w.x, bv.x);
        o.y = fmaf(xv, w.y, bv.y);
        o.z = fmaf(xv, w.z, bv.z);
        o.w = fmaf(xv, w.w, bv.w);
        __stcs(op + (size_t)i * PD4, o);   // streaming store
    }
}

extern "C" void kernel_launch(void* const* d_in, const int* in_sizes, int n_in,
                              void* d_out, int out_size) {
    const float*  x  = (const float*)d_in[0];
    const float4* W  = (const float4*)d_in[1];
    const float4* bb = (const float4*)d_in[2];
    float4* out = (float4*)d_out;

    dim3 grid(PD4 / 256, N_CHUNKS);   // 1000 x 8
    feature_expander_kernel<<<grid, 256>>>(x, W, bb, out);
}